// round 9
// baseline (speedup 1.0000x reference)
#include <cuda_runtime.h>
#include <cooperative_groups.h>
#include <cstdint>
namespace cg = cooperative_groups;

// Problem constants
#define BATCH  8
#define NPTS   32768
#define NSAMP  8192
#define FEATC  256
#define CSIZE  8                 // cluster size; 8 measured optimal (R6: 16 worse)
#define TPB    512
#define PPC    (NPTS / CSIZE)    // 4096 points per CTA
#define PPT    (PPC / TPB)       // 8 points per thread
#define NWARP  (TPB / 32)        // 16
#define NCAND  (CSIZE * NWARP)   // 128 flat candidates per iteration
#define CPL    (NCAND / 32)      // 4 candidates per lane in the combine

// Sampled indices, produced by fps_kernel, consumed by gather_kernel.
__device__ int g_idx[BATCH * NSAMP];

// ---------------------------------------------------------------------------
// FPS kernel: one 8-CTA cluster per batch. R9 structure: FLAT reduction.
// The two-level (warp -> warp0 block reduce -> fan-out) tree of R4 serialized
// ~300 cyc through a single warp; instead every warp publishes its winner
// directly to all 8 ranks, and after one cluster.sync every warp reduces the
// flat 128-candidate table (4 per lane) itself.
//
// Per iteration:
//   all warps: distance update + per-thread argmax (R4-verbatim inner loop,
//     coords carried) -> warp REDUX -> ballot+3 shfl to spread winner coords
//     -> lanes 0..7 store (v,i) + (x,y,z) into slot [rank*16+wid] of every
//     rank's double-buffered candidate table
//   cluster.sync()   (arrive.aligned doubles as the CTA barrier)
//   all warps: 4 candidates/lane local tie-break -> REDUX max/min -> winner
//     slot one-hot (indices globally unique) -> LDS.128 coord broadcast.
//
// Buffer-reuse safety: a store into buffer b at iteration k+2 happens after
// the producer passed cluster.sync(k+1), which required every CTA's arrive at
// k+1, which each CTA executes only after all its threads finished reading
// buffer b at iteration k. No overwrite hazard.
//
// Tie-break everywhere: max value, then MIN global index (= jnp.argmax
// first-occurrence; point indices globally unique -> winner slot one-hot).
// Value bits as u32 max is exact for nonnegative floats.
// Distance formula replicates XLA/NVPTX fp contraction exactly (bit-exact
// R2/R4..R8):  d = fma(dz, dz, fma(dx, dx, dy*dy))
// ---------------------------------------------------------------------------
__global__ void __cluster_dims__(CSIZE, 1, 1) __launch_bounds__(TPB, 1)
fps_kernel(const float* __restrict__ xyz)
{
    cg::cluster_group cluster = cg::this_cluster();
    const int rank  = cluster.block_rank();
    const int batch = blockIdx.x / CSIZE;
    const int tid   = threadIdx.x;
    const int lane  = tid & 31;
    const int wid   = tid >> 5;

    const float* __restrict__ xb = xyz + (size_t)batch * NPTS * 3;

    __shared__ alignas(16) float2 s_cand[2][NCAND];    // (value, index-bits)
    __shared__ alignas(16) float4 s_coord[2][NCAND];   // (x, y, z, pad)

    const int base = rank * PPC + tid;

    // Register-resident point coords and running min distances.
    float px[PPT], py[PPT], pz[PPT], md[PPT];
#pragma unroll
    for (int j = 0; j < PPT; j++) {
        const int p = base + j * TPB;
        px[j] = xb[3 * p + 0];
        py[j] = xb[3 * p + 1];
        pz[j] = xb[3 * p + 2];
        md[j] = 1e10f;            // BIG from the reference
    }

    // First sampled point is index 0 (deterministic variant).
    float cx = xb[0], cy = xb[1], cz = xb[2];
    if (rank == 0 && tid == 0) g_idx[batch * NSAMP] = 0;

    for (int k = 1; k < NSAMP; k++) {
        // --- per-thread: update min_dist, local argmax (R4-verbatim) ---
        float bv, bx, by, bz;
        int   bi;
#pragma unroll
        for (int j = 0; j < PPT; j++) {
            const float dx = __fsub_rn(px[j], cx);
            const float dy = __fsub_rn(py[j], cy);
            const float dz = __fsub_rn(pz[j], cz);
            const float d  = __fmaf_rn(dz, dz,
                              __fmaf_rn(dx, dx, __fmul_rn(dy, dy)));
            const float m  = fminf(md[j], d);
            md[j] = m;
            if (j == 0) {
                bv = m; bi = base; bx = px[0]; by = py[0]; bz = pz[0];
            } else if (m > bv) {   // strict >: earlier (lower) index wins ties
                bv = m; bi = base + j * TPB; bx = px[j]; by = py[j]; bz = pz[j];
            }
        }

        // --- warp argmax via REDUX ---
        const uint32_t uv = __float_as_uint(bv);            // bv >= 0
        const uint32_t kv = __reduce_max_sync(0xffffffffu, uv);
        const uint32_t cand = (uv == kv) ? (uint32_t)bi : 0xffffffffu;
        const uint32_t ki = __reduce_min_sync(0xffffffffu, cand);

        // --- spread winner coords, publish to all ranks (flat fan-out) ---
        const uint32_t mw  = __ballot_sync(0xffffffffu, (uint32_t)bi == ki);
        const int      src = __ffs(mw) - 1;
        const float wx = __shfl_sync(0xffffffffu, bx, src);
        const float wy = __shfl_sync(0xffffffffu, by, src);
        const float wz = __shfl_sync(0xffffffffu, bz, src);

        const int b    = k & 1;
        const int slot = rank * NWARP + wid;
        if (lane < CSIZE) {
            float2* c = (float2*)cluster.map_shared_rank(
                (void*)&s_cand[b][slot], lane);
            *c = make_float2(__uint_as_float(kv), __uint_as_float(ki));
            float4* q = (float4*)cluster.map_shared_rank(
                (void*)&s_coord[b][slot], lane);
            *q = make_float4(wx, wy, wz, 0.f);
        }

        // CTA barrier + cluster barrier + DSMEM release/acquire, all in one.
        cluster.sync();

        // --- flat combine: 4 candidates per lane over the 128-entry table ---
        float    lv = -1.0f;
        uint32_t li = 0xffffffffu;
        int      ms = 0;
#pragma unroll
        for (int t = 0; t < CPL; t++) {
            const int s = lane * CPL + t;
            const float2 c  = s_cand[b][s];
            const uint32_t ci = __float_as_uint(c.y);
            if (c.x > lv || (c.x == lv && ci < li)) {
                lv = c.x; li = ci; ms = s;
            }
        }
        const uint32_t uv3 = __float_as_uint(lv);
        const uint32_t kv3 = __reduce_max_sync(0xffffffffu, uv3);
        const uint32_t c3  = (uv3 == kv3) ? li : 0xffffffffu;
        const uint32_t ki3 = __reduce_min_sync(0xffffffffu, c3);
        // Winner index globally unique -> exactly one lane holds it, and for
        // that lane it is its local best.
        const uint32_t m3  = __ballot_sync(0xffffffffu,
                                           li == ki3 && uv3 == kv3);
        const int sl3  = __ffs(m3) - 1;
        const int wslt = __shfl_sync(0xffffffffu, ms, sl3);
        const float4 q = s_coord[b][wslt];                  // LDS broadcast
        cx = q.x; cy = q.y; cz = q.z;

        if (rank == 0 && tid == 0) g_idx[batch * NSAMP + k] = (int)ki3;
    }
}

// ---------------------------------------------------------------------------
// Gather kernel: one block per sampled row. 256 feature floats (64 x float4)
// plus the 3 xyz floats. Output: [xyz (B,S,3)] then [feature (B,S,256)].
// ---------------------------------------------------------------------------
__global__ void __launch_bounds__(64)
gather_kernel(const float* __restrict__ xyz, const float* __restrict__ feat,
              float* __restrict__ out)
{
    const int row = blockIdx.x;          // 0 .. BATCH*NSAMP-1
    const int b = row / NSAMP;
    const int p = g_idx[row];

    float* out_xyz  = out;
    float* out_feat = out + (size_t)BATCH * NSAMP * 3;

    const float4* src = (const float4*)(feat + ((size_t)b * NPTS + p) * FEATC);
    float4*       dst = (float4*)(out_feat + (size_t)row * FEATC);
    dst[threadIdx.x] = src[threadIdx.x];

    if (threadIdx.x < 3) {
        out_xyz[(size_t)row * 3 + threadIdx.x] =
            xyz[((size_t)b * NPTS + p) * 3 + threadIdx.x];
    }
}

extern "C" void kernel_launch(void* const* d_in, const int* in_sizes, int n_in,
                              void* d_out, int out_size)
{
    const float* xyz  = (const float*)d_in[0];
    const float* feat = (const float*)d_in[1];
    float*       out  = (float*)d_out;

    fps_kernel<<<BATCH * CSIZE, TPB>>>(xyz);
    gather_kernel<<<BATCH * NSAMP, 64>>>(xyz, feat, out);
}

// round 11
// speedup vs baseline: 1.0961x; 1.0961x over previous
#include <cuda_runtime.h>
#include <cooperative_groups.h>
#include <cstdint>
namespace cg = cooperative_groups;

// Problem constants
#define BATCH  8
#define NPTS   32768
#define NSAMP  8192
#define FEATC  256
#define CSIZE  8                 // cluster size; 8 measured optimal (R6: 16 worse)
#define TPB    512
#define PPC    (NPTS / CSIZE)    // 4096 points per CTA
#define PPT    (PPC / TPB)       // 8 points per thread
#define NWARP  (TPB / 32)        // 16

// Sampled indexes, produced by fps_kernel, consumed by gather_kernel.
__device__ int g_idx[BATCH * NSAMP];

// ---------------------------------------------------------------------------
// FPS kernel: one 8-CTA cluster per batch. R4-proven skeleton (6917us):
// two-level reduction + single-warp fan-out + cluster.sync. Measured-dead
// alternatives: mbarrier exchange (R5/R7), cluster-16 (R6), f32x2 (R8),
// flat fan-out (R9, DSMEM-BW bound). R10 change vs R4: inner loop tracks
// only (value, local j); the unique warp-REDUX winner lane recovers coords
// post-hoc (removes ~24 select instrs/thread from the issue-bound phase).
//
// Per iteration:
//   all warps: distance update + per-thread argmax (value + local j)
//     -> warp REDUX (max value bits, min index among matches) -> winner lane
//     recovers coords, writes s_warp[wid] -> __syncthreads
//   warp0: block REDUX over 16 warp winners; lanes 0..7 fan the CTA
//     candidate out to every rank's double-buffered DSMEM slot
//   cluster.sync()
//   all warps: REDUX combine over the 8 slots -> global winner + coords.
//
// Tie-break everywhere: max value, then MIN global index (= jnp.argmax
// first-occurrence; point indices globally unique so matches are one-hot).
// Value bits as u32 max is exact for nonnegative floats.
// Distance formula replicates XLA/NVPTX fp contraction exactly (bit-exact
// R2/R4..R9):  d = fma(dz, dz, fma(dx, dx, dy*dy))
// ---------------------------------------------------------------------------
__global__ void __cluster_dims__(CSIZE, 1, 1) __launch_bounds__(TPB, 1)
fps_kernel(const float* __restrict__ xyz)
{
    cg::cluster_group cluster = cg::this_cluster();
    const int rank  = cluster.block_rank();
    const int batch = blockIdx.x / CSIZE;
    const int tid   = threadIdx.x;
    const int lane  = tid & 31;
    const int wid   = tid >> 5;

    const float* __restrict__ xb = xyz + (size_t)batch * NPTS * 3;

    __shared__ alignas(16) float s_warp[NWARP][8];      // per-warp winners
    __shared__ alignas(16) float s_slot[2][CSIZE][8];   // cluster candidates

    const int base = rank * PPC + tid;

    // Register-resident point coords and running min distances.
    float px[PPT], py[PPT], pz[PPT], md[PPT];
#pragma unroll
    for (int j = 0; j < PPT; j++) {
        const int p = base + j * TPB;
        px[j] = xb[3 * p + 0];
        py[j] = xb[3 * p + 1];
        pz[j] = xb[3 * p + 2];
        md[j] = 1e10f;            // BIG from the reference
    }

    // First sampled point is index 0 (deterministic variant).
    float cx = xb[0], cy = xb[1], cz = xb[2];
    if (rank == 0 && tid == 0) g_idx[batch * NSAMP] = 0;

    for (int k = 1; k < NSAMP; k++) {
        // --- per-thread: update min_dist, local argmax (value + local j) ---
        float bv;
        int   bj;
#pragma unroll
        for (int j = 0; j < PPT; j++) {
            const float dx = __fsub_rn(px[j], cx);
            const float dy = __fsub_rn(py[j], cy);
            const float dz = __fsub_rn(pz[j], cz);
            const float d  = __fmaf_rn(dz, dz,
                              __fmaf_rn(dx, dx, __fmul_rn(dy, dy)));
            const float m  = fminf(md[j], d);
            md[j] = m;
            if (j == 0) {
                bv = m; bj = 0;
            } else if (m > bv) {   // strict >: earlier (lower) index wins ties
                bv = m; bj = j;
            }
        }
        const uint32_t bi = (uint32_t)(base + bj * TPB);

        // --- warp argmax via REDUX ---
        const uint32_t uv = __float_as_uint(bv);            // bv >= 0
        const uint32_t kv = __reduce_max_sync(0xffffffffu, uv);
        const uint32_t cand = (uv == kv) ? bi : 0xffffffffu;
        const uint32_t ki = __reduce_min_sync(0xffffffffu, cand);
        if (bi == ki) {            // unique winner lane: recover coords here
            float bx = px[0], by = py[0], bz = pz[0];
#pragma unroll
            for (int j = 1; j < PPT; j++) {
                if (bj == j) { bx = px[j]; by = py[j]; bz = pz[j]; }
            }
            *(float4*)&s_warp[wid][0] =
                make_float4(__uint_as_float(kv), __uint_as_float(ki), bx, by);
            s_warp[wid][4] = bz;
        }
        __syncthreads();

        const int b = k & 1;

        // --- warp0: block argmax over 16 warp winners, fan out to all ranks ---
        if (wid == 0) {
            float sv = 0.f, sx = 0.f, sy = 0.f, sz = 0.f;
            uint32_t si = 0xffffffffu;
            if (lane < NWARP) {
                const float4 t = *(const float4*)&s_warp[lane][0];
                sv = t.x; si = __float_as_uint(t.y); sx = t.z; sy = t.w;
                sz = s_warp[lane][4];
            }
            const uint32_t uv2 = __float_as_uint(sv);
            const uint32_t kv2 = __reduce_max_sync(0xffffffffu, uv2);
            const uint32_t c2  = (uv2 == kv2) ? si : 0xffffffffu;
            const uint32_t ki2 = __reduce_min_sync(0xffffffffu, c2);
            const uint32_t m2  = __ballot_sync(0xffffffffu, c2 == ki2); // one-hot
            const int src = __ffs(m2) - 1;
            const float wx = __shfl_sync(0xffffffffu, sx, src);
            const float wy = __shfl_sync(0xffffffffu, sy, src);
            const float wz = __shfl_sync(0xffffffffu, sz, src);
            if (lane < CSIZE) {
                // lane r writes this CTA's candidate into rank r's slot row.
                // Ordering/visibility provided by cluster.sync() below.
                float* dst = (float*)cluster.map_shared_rank(
                    (void*)&s_slot[b][rank][0], lane);
                *(float4*)dst =
                    make_float4(__uint_as_float(kv2), __uint_as_float(ki2), wx, wy);
                dst[4] = wz;
            }
        }

        // release DSMEM stores + cluster barrier + acquire remote stores
        cluster.sync();

        // --- per-warp REDUX combine over the CSIZE slots ---
        float sv = 0.f, sx = 0.f, sy = 0.f, sz = 0.f;
        uint32_t si = 0xffffffffu;
        if (lane < CSIZE) {
            const float4 t = *(const float4*)&s_slot[b][lane][0];
            sv = t.x; si = __float_as_uint(t.y); sx = t.z; sy = t.w;
            sz = s_slot[b][lane][4];
        }
        const uint32_t uv3 = __float_as_uint(sv);
        const uint32_t kv3 = __reduce_max_sync(0xffffffffu, uv3);
        const uint32_t c3  = (uv3 == kv3) ? si : 0xffffffffu;
        const uint32_t ki3 = __reduce_min_sync(0xffffffffu, c3);
        const uint32_t m3  = __ballot_sync(0xffffffffu, c3 == ki3);    // one-hot
        const int src3 = __ffs(m3) - 1;
        cx = __shfl_sync(0xffffffffu, sx, src3);
        cy = __shfl_sync(0xffffffffu, sy, src3);
        cz = __shfl_sync(0xffffffffu, sz, src3);

        if (rank == 0 && tid == 0) g_idx[batch * NSAMP + k] = (int)ki3;
    }
}

// ---------------------------------------------------------------------------
// Gather kernel: one block per sampled row. 256 feature floats (64 x float4)
// plus the 3 xyz floats. Output: [xyz (B,S,3)] then [feature (B,S,256)].
// ---------------------------------------------------------------------------
__global__ void __launch_bounds__(64)
gather_kernel(const float* __restrict__ xyz, const float* __restrict__ feat,
              float* __restrict__ out)
{
    const int row = blockIdx.x;          // 0 .. BATCH*NSAMP-1
    const int b = row / NSAMP;
    const int p = g_idx[row];

    float* out_xyz  = out;
    float* out_feat = out + (size_t)BATCH * NSAMP * 3;

    const float4* src = (const float4*)(feat + ((size_t)b * NPTS + p) * FEATC);
    float4*       dst = (float4*)(out_feat + (size_t)row * FEATC);
    dst[threadIdx.x] = src[threadIdx.x];

    if (threadIdx.x < 3) {
        out_xyz[(size_t)row * 3 + threadIdx.x] =
            xyz[((size_t)b * NPTS + p) * 3 + threadIdx.x];
    }
}

extern "C" void kernel_launch(void* const* d_in, const int* in_sizes, int n_in,
                              void* d_out, int out_size)
{
    const float* xyz  = (const float*)d_in[0];
    const float* feat = (const float*)d_in[1];
    float*       out  = (float*)d_out;

    fps_kernel<<<BATCH * CSIZE, TPB>>>(xyz);
    gather_kernel<<<BATCH * NSAMP, 64>>>(xyz, feat, out);
}

// round 12
// speedup vs baseline: 1.1773x; 1.0741x over previous
#include <cuda_runtime.h>
#include <cooperative_groups.h>
#include <cstdint>
namespace cg = cooperative_groups;

// Problem constants
#define BATCH  8
#define NPTS   32768
#define NSAMP  8192
#define FEATC  256
#define CSIZE  8                 // cluster size; 8 measured optimal (R6: 16 worse)
#define TPB    512
#define PPC    (NPTS / CSIZE)    // 4096 points per CTA
#define PPT    (PPC / TPB)       // 8 points per thread
#define NWARP  (TPB / 32)        // 16

// Sampled indices, produced by fps_kernel, consumed by gather_kernel.
__device__ int g_idx[BATCH * NSAMP];

// ---------------------------------------------------------------------------
// FPS kernel: one 8-CTA cluster per batch. This is the R4 design (6917us),
// the measured optimum of this space. Measured-dead alternatives: mbarrier
// exchange all-poll/warp0-poll (R5/R7), cluster-16 (R6), f32x2 (R8), flat
// fan-out (R9, DSMEM-BW bound), coord-trim in the inner loop (R10/R11).
// R12 delta vs R4: warp0's remote slot pointers (mapa) are precomputed once
// before the loop (both buffers), removing mapa+address arith from the
// serial warp0 phase each iteration.
//
// Per iteration:
//   all warps: distance update + per-thread argmax (coords carried via
//     select -- measured faster than post-hoc recovery) -> warp REDUX
//     (max value bits, then min index among matches) -> winner lane writes
//     s_warp[wid] -> __syncthreads
//   warp0: block REDUX over 16 warp winners; lanes 0..7 store the CTA
//     candidate to every rank's double-buffered DSMEM slot (precomputed ptrs)
//   cluster.sync()
//   all warps: REDUX combine over the 8 slots -> global winner + coords.
//
// Tie-break everywhere: max value, then MIN global index (= jnp.argmax
// first-occurrence; point indices globally unique so matches are one-hot).
// Value bits as u32 max is exact for nonnegative floats.
// Distance formula replicates XLA/NVPTX fp contraction exactly (bit-exact
// R2/R4..R11):  d = fma(dz, dz, fma(dx, dx, dy*dy))
// ---------------------------------------------------------------------------
__global__ void __cluster_dims__(CSIZE, 1, 1) __launch_bounds__(TPB, 1)
fps_kernel(const float* __restrict__ xyz)
{
    cg::cluster_group cluster = cg::this_cluster();
    const int rank  = cluster.block_rank();
    const int batch = blockIdx.x / CSIZE;
    const int tid   = threadIdx.x;
    const int lane  = tid & 31;
    const int wid   = tid >> 5;

    const float* __restrict__ xb = xyz + (size_t)batch * NPTS * 3;

    __shared__ alignas(16) float s_warp[NWARP][8];      // per-warp winners
    __shared__ alignas(16) float s_slot[2][CSIZE][8];   // cluster candidates

    const int base = rank * PPC + tid;

    // Precompute remote slot pointers for the publish fan-out (warp0 lanes
    // 0..7 use them): lane r targets rank r's slot row for this CTA's rank,
    // one pointer per double-buffer.
    float* dst0 = nullptr;
    float* dst1 = nullptr;
    if (wid == 0 && lane < CSIZE) {
        dst0 = (float*)cluster.map_shared_rank((void*)&s_slot[0][rank][0], lane);
        dst1 = (float*)cluster.map_shared_rank((void*)&s_slot[1][rank][0], lane);
    }

    // Register-resident point coords and running min distances.
    float px[PPT], py[PPT], pz[PPT], md[PPT];
#pragma unroll
    for (int j = 0; j < PPT; j++) {
        const int p = base + j * TPB;
        px[j] = xb[3 * p + 0];
        py[j] = xb[3 * p + 1];
        pz[j] = xb[3 * p + 2];
        md[j] = 1e10f;            // BIG from the reference
    }

    // First sampled point is index 0 (deterministic variant).
    float cx = xb[0], cy = xb[1], cz = xb[2];
    if (rank == 0 && tid == 0) g_idx[batch * NSAMP] = 0;

    for (int k = 1; k < NSAMP; k++) {
        // --- per-thread: update min_dist, local argmax (value, index, coords) ---
        float bv, bx, by, bz;
        int   bi;
#pragma unroll
        for (int j = 0; j < PPT; j++) {
            const float dx = __fsub_rn(px[j], cx);
            const float dy = __fsub_rn(py[j], cy);
            const float dz = __fsub_rn(pz[j], cz);
            const float d  = __fmaf_rn(dz, dz,
                              __fmaf_rn(dx, dx, __fmul_rn(dy, dy)));
            const float m  = fminf(md[j], d);
            md[j] = m;
            if (j == 0) {
                bv = m; bi = base; bx = px[0]; by = py[0]; bz = pz[0];
            } else if (m > bv) {   // strict >: earlier (lower) index wins ties
                bv = m; bi = base + j * TPB; bx = px[j]; by = py[j]; bz = pz[j];
            }
        }

        // --- warp argmax via REDUX ---
        const uint32_t uv = __float_as_uint(bv);            // bv >= 0
        const uint32_t kv = __reduce_max_sync(0xffffffffu, uv);
        const uint32_t cand = (uv == kv) ? (uint32_t)bi : 0xffffffffu;
        const uint32_t ki = __reduce_min_sync(0xffffffffu, cand);
        if ((uint32_t)bi == ki) {                           // unique winner lane
            *(float4*)&s_warp[wid][0] =
                make_float4(__uint_as_float(kv), __uint_as_float(ki), bx, by);
            s_warp[wid][4] = bz;
        }
        __syncthreads();

        const int b = k & 1;

        // --- warp0: block argmax over 16 warp winners, fan out to all ranks ---
        if (wid == 0) {
            float sv = 0.f, sx = 0.f, sy = 0.f, sz = 0.f;
            uint32_t si = 0xffffffffu;
            if (lane < NWARP) {
                const float4 t = *(const float4*)&s_warp[lane][0];
                sv = t.x; si = __float_as_uint(t.y); sx = t.z; sy = t.w;
                sz = s_warp[lane][4];
            }
            const uint32_t uv2 = __float_as_uint(sv);
            const uint32_t kv2 = __reduce_max_sync(0xffffffffu, uv2);
            const uint32_t c2  = (uv2 == kv2) ? si : 0xffffffffu;
            const uint32_t ki2 = __reduce_min_sync(0xffffffffu, c2);
            const uint32_t m2  = __ballot_sync(0xffffffffu, c2 == ki2); // one-hot
            const int src = __ffs(m2) - 1;
            const float wx = __shfl_sync(0xffffffffu, sx, src);
            const float wy = __shfl_sync(0xffffffffu, sy, src);
            const float wz = __shfl_sync(0xffffffffu, sz, src);
            if (lane < CSIZE) {
                // Precomputed remote pointer; ordering/visibility via
                // cluster.sync() below.
                float* dst = b ? dst1 : dst0;
                *(float4*)dst =
                    make_float4(__uint_as_float(kv2), __uint_as_float(ki2), wx, wy);
                dst[4] = wz;
            }
        }

        // release DSMEM stores + cluster barrier + acquire remote stores
        cluster.sync();

        // --- per-warp REDUX combine over the CSIZE slots ---
        float sv = 0.f, sx = 0.f, sy = 0.f, sz = 0.f;
        uint32_t si = 0xffffffffu;
        if (lane < CSIZE) {
            const float4 t = *(const float4*)&s_slot[b][lane][0];
            sv = t.x; si = __float_as_uint(t.y); sx = t.z; sy = t.w;
            sz = s_slot[b][lane][4];
        }
        const uint32_t uv3 = __float_as_uint(sv);
        const uint32_t kv3 = __reduce_max_sync(0xffffffffu, uv3);
        const uint32_t c3  = (uv3 == kv3) ? si : 0xffffffffu;
        const uint32_t ki3 = __reduce_min_sync(0xffffffffu, c3);
        const uint32_t m3  = __ballot_sync(0xffffffffu, c3 == ki3);    // one-hot
        const int src3 = __ffs(m3) - 1;
        cx = __shfl_sync(0xffffffffu, sx, src3);
        cy = __shfl_sync(0xffffffffu, sy, src3);
        cz = __shfl_sync(0xffffffffu, sz, src3);

        if (rank == 0 && tid == 0) g_idx[batch * NSAMP + k] = (int)ki3;
    }
}

// ---------------------------------------------------------------------------
// Gather kernel: one block per sampled row. 256 feature floats (64 x float4)
// plus the 3 xyz floats. Output: [xyz (B,S,3)] then [feature (B,S,256)].
// ---------------------------------------------------------------------------
__global__ void __launch_bounds__(64)
gather_kernel(const float* __restrict__ xyz, const float* __restrict__ feat,
              float* __restrict__ out)
{
    const int row = blockIdx.x;          // 0 .. BATCH*NSAMP-1
    const int b = row / NSAMP;
    const int p = g_idx[row];

    float* out_xyz  = out;
    float* out_feat = out + (size_t)BATCH * NSAMP * 3;

    const float4* src = (const float4*)(feat + ((size_t)b * NPTS + p) * FEATC);
    float4*       dst = (float4*)(out_feat + (size_t)row * FEATC);
    dst[threadIdx.x] = src[threadIdx.x];

    if (threadIdx.x < 3) {
        out_xyz[(size_t)row * 3 + threadIdx.x] =
            xyz[((size_t)b * NPTS + p) * 3 + threadIdx.x];
    }
}

extern "C" void kernel_launch(void* const* d_in, const int* in_sizes, int n_in,
                              void* d_out, int out_size)
{
    const float* xyz  = (const float*)d_in[0];
    const float* feat = (const float*)d_in[1];
    float*       out  = (float*)d_out;

    fps_kernel<<<BATCH * CSIZE, TPB>>>(xyz);
    gather_kernel<<<BATCH * NSAMP, 64>>>(xyz, feat, out);
}